// round 12
// baseline (speedup 1.0000x reference)
#include <cuda_runtime.h>
#include <cuda_bf16.h>
#include <cstdint>

// EdgeConv fused, round 12: cp.async (LDGSTS) gather pipeline, depth 4, with
// read-side window assembly (per-lane index map + zero word). GEMM and preps
// are the proven round-10 versions.
// out[p][o] = sum_cc E[p][cc] * Wt[cc][o] + bias[o]
//   E = [gsum | x], Wt[cc<64] = W[o][cc]/20, Wt[cc>=64] = W[o][cc]-W[o][cc-64]

#define BB 4
#define NN 32768
#define KK 20
#define CC 64
#define C2 128
#define OUTD 64
#define TP 128
#define THREADS 256
#define ROWB 256        // A/W image row bytes; swizzle k' = (k&8)|((k^row)&7)

// smem byte offsets (main kernel)
#define OFF_W_HI  0
#define OFF_W_LO  16384
#define OFF_A_HI  32768
#define OFF_A_LO  65536
#define OFF_SCR   98304           // 8 warps x 4 buffers x 88 floats = 11264 B
#define OFF_BIAS  109568
#define SMEM_BYTES (OFF_BIAS + 256)   // 109824 -> 2 CTAs/SM

__device__ float g_xv[(size_t)BB * NN * 20];               // variant table 10.5 MB
__device__ __align__(16) unsigned short g_Whi[OUTD * C2];  // swizzled W images
__device__ __align__(16) unsigned short g_Wlo[OUTD * C2];

// ---------------- helpers ----------------
__device__ __forceinline__ unsigned smem_u32(const void* p) {
    unsigned a;
    asm("{ .reg .u64 t; cvta.to.shared.u64 t, %1; cvt.u32.u64 %0, t; }" : "=r"(a) : "l"(p));
    return a;
}
__device__ __forceinline__ void ldsm4(unsigned* r, unsigned addr) {
    asm volatile("ldmatrix.sync.aligned.m8n8.x4.shared.b16 {%0,%1,%2,%3}, [%4];"
                 : "=r"(r[0]), "=r"(r[1]), "=r"(r[2]), "=r"(r[3]) : "r"(addr));
}
__device__ __forceinline__ void mma16816(float* d, const unsigned* a,
                                         unsigned b0, unsigned b1) {
    asm volatile(
        "mma.sync.aligned.m16n8k16.row.col.f32.bf16.bf16.f32 "
        "{%0,%1,%2,%3}, {%4,%5,%6,%7}, {%8,%9}, {%0,%1,%2,%3};"
        : "+f"(d[0]), "+f"(d[1]), "+f"(d[2]), "+f"(d[3])
        : "r"(a[0]), "r"(a[1]), "r"(a[2]), "r"(a[3]), "r"(b0), "r"(b1));
}
__device__ __forceinline__ unsigned pack_hi(float a, float b, float& ra, float& rb) {
    __nv_bfloat16 ha = __float2bfloat16(a), hb = __float2bfloat16(b);
    ra = a - __bfloat162float(ha);
    rb = b - __bfloat162float(hb);
    return ((unsigned)__bfloat16_as_ushort(hb) << 16) | (unsigned)__bfloat16_as_ushort(ha);
}
__device__ __forceinline__ unsigned pack_lo(float ra, float rb) {
    __nv_bfloat16 la = __float2bfloat16(ra);
    __nv_bfloat16 lb = __float2bfloat16(rb);
    return ((unsigned)__bfloat16_as_ushort(lb) << 16) | (unsigned)__bfloat16_as_ushort(la);
}
__device__ __forceinline__ unsigned swz(int r, int k) {
    return (unsigned)(r * ROWB + (((k & 8) | ((k ^ r) & 7)) << 4));
}
__device__ __forceinline__ void cpasync16(unsigned dst, const void* src) {
    asm volatile("cp.async.ca.shared.global [%0], [%1], 16;"
                 :: "r"(dst), "l"(src) : "memory");
}
#define CP_COMMIT() asm volatile("cp.async.commit_group;" ::: "memory")
#define CP_WAIT3()  asm volatile("cp.async.wait_group 3;" ::: "memory")

// window c -> raw-piece indices. raw[j*4+k] = xv piece k of slot j; raw[80] = 0.
__device__ __forceinline__ void widx(int c, int& iA, int& iB) {
    int s  = (5 * c) >> 4;
    int v  = s % 5;
    int ls = 5 * c - 16 * s;
    if (ls == 15 - v && v < 4) { iA = 4 * s + 3; iB = 4 * (s + 1); }
    else {
        int k = (ls == 0) ? 0 : (ls == 5 - v) ? 1 : (ls == 10 - v) ? 2 : 3;
        iA = 4 * s + k; iB = 80;
    }
}

// ---------------- prep 1: window-variant table (round-10 version) -----------
__global__ __launch_bounds__(256)
void edgeconv_xv_kernel(const float* __restrict__ x)
{
    __shared__ float s4[64 * 16];
    const int tid = threadIdx.x;
    const int R0  = blockIdx.x * 64;

    const float4* __restrict__ x4 = (const float4*)x + (size_t)R0 * 16;
    #pragma unroll
    for (int i = 0; i < 4; ++i) {
        int idx = tid + 256 * i;
        float4 v = x4[idx];
        s4[idx] = (v.x + v.y) + (v.z + v.w);
    }
    __syncthreads();

    #pragma unroll
    for (int pass = 0; pass < 2; ++pass) {
        int item = tid + pass * 256;
        if (item < 320) {
            int r = item / 5;
            int v = item - 5 * r;
            const float* s = &s4[r * 16];
            const int i1 = 4 - v, i2 = 9 - v, i3 = 14 - v;
            float cum = 0.0f, P1 = 0.0f, P2 = 0.0f, P3 = 0.0f;
            #pragma unroll
            for (int i = 0; i < 16; ++i) {
                cum += s[i];
                if (i == i1) P1 = cum;
                if (i == i2) P2 = cum;
                if (i == i3) P3 = cum;
            }
            float4 o;
            o.x = P1;
            o.y = P2 - P1;
            o.z = P3 - P2;
            o.w = cum - P3;
            *(float4*)&g_xv[(size_t)(R0 + r) * 20 + 4 * v] = o;
        }
    }
}

// ---------------- prep 2: combined weights -> bf16 hi/lo swizzled images ----
__global__ void edgeconv_prepw_kernel(const float* __restrict__ W)
{
    int i = blockIdx.x * blockDim.x + threadIdx.x;
    if (i < OUTD * C2) {
        int o = i >> 7, cc = i & 127;
        float w = W[o * C2 + cc];
        if (cc < CC) w *= (1.0f / (float)KK);
        else         w -= W[o * C2 + (cc - CC)];
        __nv_bfloat16 h = __float2bfloat16(w);
        __nv_bfloat16 l = __float2bfloat16(w - __bfloat162float(h));
        unsigned byteoff = swz(o, cc >> 3) + ((cc & 7) << 1);
        g_Whi[byteoff >> 1] = __bfloat16_as_ushort(h);
        g_Wlo[byteoff >> 1] = __bfloat16_as_ushort(l);
    }
}

// ---------------- main fused kernel ----------------
__global__ __launch_bounds__(THREADS, 2)
void edgeconv_fused_kernel(const float* __restrict__ x,
                           const int* __restrict__ adj,
                           const float* __restrict__ bias,
                           float* __restrict__ out)
{
    extern __shared__ __align__(16) char smem[];
    const unsigned smem_base = smem_u32(smem);

    const int tid = threadIdx.x;
    const int wid = tid >> 5;
    const int lid = tid & 31;
    const int gp0 = blockIdx.x * TP;
    const int b   = gp0 >> 15;
    const int n0  = gp0 & (NN - 1);

    // ---- copy prepped W images + bias; zero cp.async buffers ----
    {
        const uint4* sh = (const uint4*)g_Whi;
        const uint4* sl = (const uint4*)g_Wlo;
        uint4* dh = (uint4*)(smem + OFF_W_HI);
        uint4* dl = (uint4*)(smem + OFF_W_LO);
        #pragma unroll
        for (int i = tid; i < (OUTD * C2) / 8; i += THREADS) { dh[i] = sh[i]; dl[i] = sl[i]; }
    }
    if (tid < OUTD) ((float*)(smem + OFF_BIAS))[tid] = bias[tid];

    float* __restrict__ swf = (float*)(smem + OFF_SCR) + wid * 352;  // 4 x 88 floats
    const unsigned sw_u32 = smem_base + OFF_SCR + wid * 1408;
    #pragma unroll
    for (int i = lid; i < 352; i += 32) swf[i] = 0.0f;   // incl. zero word at [d*88+80]
    __syncwarp();

    // ---- gather: warp owns points [16*wid, 16*wid+16), cp.async depth-4 ----
    const float4* __restrict__ xv4 = (const float4*)g_xv + (size_t)b * NN * 5;
    const float2* __restrict__ xb2 = (const float2*)(x + (size_t)b * NN * CC);

    const bool act = (lid < KK);
    const int  vS  = act ? (lid % 5) : 0;

    int iA0, iB0, iA1, iB1;
    widx(2 * lid,     iA0, iB0);
    widx(2 * lid + 1, iA1, iB1);

    int a[16];
    #pragma unroll
    for (int pi = 0; pi < 16; ++pi) {
        int gp = gp0 + 16 * wid + pi;
        a[pi] = act ? adj[(size_t)gp * KK + lid] : 0;
    }

    // prologue: issue points 0..3 (one commit-group per point)
    #pragma unroll
    for (int d = 0; d < 4; ++d) {
        if (act) cpasync16(sw_u32 + d * 352 + lid * 16, &xv4[(size_t)a[d] * 5 + vS]);
        CP_COMMIT();
    }

    const size_t xrow = (size_t)(n0 + 16 * wid) * 32 + lid;
    float2 xc = xb2[xrow + 0 * 32];
    float2 xd = xb2[xrow + 1 * 32];

    #pragma unroll 4
    for (int pi = 0; pi < 16; ++pi) {
        const int p = 16 * wid + pi;

        CP_WAIT3();        // point pi's buffer complete
        __syncwarp();

        const float* buf = swf + (pi & 3) * 88;
        float wA = buf[iA0] + buf[iB0];
        float wB = buf[iA1] + buf[iB1];

        // prefetch center x (2-point register lead; coalesced, cheap)
        float2 xe = make_float2(0.f, 0.f);
        if (pi < 14) xe = xb2[xrow + (size_t)(pi + 2) * 32];

        float rg0, rg1, rx0, rx1;
        unsigned hp_g = pack_hi(wA, wB, rg0, rg1);
        unsigned hp_x = pack_hi(xc.x, xc.y, rx0, rx1);
        unsigned lp_g = pack_lo(rg0, rg1);
        unsigned lp_x = pack_lo(rx0, rx1);

        const int w4 = (lid & 3) << 2;
        unsigned offg = swz(p, lid >> 2)       + w4;
        unsigned offx = swz(p, 8 + (lid >> 2)) + w4;
        *(unsigned*)(smem + OFF_A_HI + offg) = hp_g;
        *(unsigned*)(smem + OFF_A_LO + offg) = lp_g;
        *(unsigned*)(smem + OFF_A_HI + offx) = hp_x;
        *(unsigned*)(smem + OFF_A_LO + offx) = lp_x;

        __syncwarp();      // all lanes' reads of buf[pi&3] done

        if (act && pi + 4 < 16)
            cpasync16(sw_u32 + ((pi + 4) & 3) * 352 + lid * 16,
                      &xv4[(size_t)a[pi + 4] * 5 + vS]);
        CP_COMMIT();       // keep group count aligned (empty groups ok)

        xc = xd; xd = xe;
    }

    __syncthreads();

    // ---- GEMM: warps 4M x 2N, warp tile 32x32, K=128, bf16 3-product split ----
    const int mg = wid & 3;
    const int ng = wid >> 2;
    const int lrow  = (lid & 7) + 8 * ((lid >> 3) & 1);
    const int khalf = lid >> 4;

    const int rA0 = 32 * mg + lrow;
    const int rB0 = 32 * ng + (lid & 15);

    float d[2][4][4];
    #pragma unroll
    for (int mt = 0; mt < 2; ++mt)
        #pragma unroll
        for (int nt = 0; nt < 4; ++nt)
            #pragma unroll
            for (int e = 0; e < 4; ++e) d[mt][nt][e] = 0.0f;

    #pragma unroll 2
    for (int ks = 0; ks < 8; ++ks) {
        const int k = 2 * ks + khalf;
        const unsigned a0 = smem_base + OFF_A_HI + swz(rA0, k);
        const unsigned a1 = smem_base + OFF_A_HI + swz(rA0 + 16, k);
        const unsigned b0 = smem_base + OFF_W_HI + swz(rB0, k);
        const unsigned b1 = smem_base + OFF_W_HI + swz(rB0 + 16, k);

        unsigned ah[2][4], al[2][4];
        ldsm4(ah[0], a0);
        ldsm4(ah[1], a1);
        ldsm4(al[0], a0 + (OFF_A_LO - OFF_A_HI));
        ldsm4(al[1], a1 + (OFF_A_LO - OFF_A_HI));

        unsigned bh01[4], bh23[4], bl01[4], bl23[4];
        ldsm4(bh01, b0);
        ldsm4(bh23, b1);
        ldsm4(bl01, b0 + (OFF_W_LO - OFF_W_HI));
        ldsm4(bl23, b1 + (OFF_W_LO - OFF_W_HI));

        unsigned bhf[4][2] = {{bh01[0], bh01[2]}, {bh01[1], bh01[3]},
                              {bh23[0], bh23[2]}, {bh23[1], bh23[3]}};
        unsigned blf[4][2] = {{bl01[0], bl01[2]}, {bl01[1], bl01[3]},
                              {bl23[0], bl23[2]}, {bl23[1], bl23[3]}};

        #pragma unroll
        for (int mt = 0; mt < 2; ++mt) {
            #pragma unroll
            for (int nt = 0; nt < 4; ++nt) {
                mma16816(d[mt][nt], ah[mt], bhf[nt][0], bhf[nt][1]);
                mma16816(d[mt][nt], al[mt], bhf[nt][0], bhf[nt][1]);
                mma16816(d[mt][nt], ah[mt], blf[nt][0], blf[nt][1]);
            }
        }
    }

    // ---- epilogue: bias + store ----
    const float* sBias = (const float*)(smem + OFF_BIAS);
    const int g  = lid >> 2;
    const int oc = 2 * (lid & 3);
    #pragma unroll
    for (int mt = 0; mt < 2; ++mt) {
        const int prow = gp0 + 32 * mg + 16 * mt + g;
        #pragma unroll
        for (int nt = 0; nt < 4; ++nt) {
            const int o = 32 * ng + 8 * nt + oc;
            float2 bb = *(const float2*)&sBias[o];
            float2 r0, r1;
            r0.x = d[mt][nt][0] + bb.x;  r0.y = d[mt][nt][1] + bb.y;
            r1.x = d[mt][nt][2] + bb.x;  r1.y = d[mt][nt][3] + bb.y;
            *(float2*)&out[(size_t)prow * OUTD + o]       = r0;
            *(float2*)&out[(size_t)(prow + 8) * OUTD + o] = r1;
        }
    }
}

extern "C" void kernel_launch(void* const* d_in, const int* in_sizes, int n_in,
                              void* d_out, int out_size)
{
    (void)in_sizes; (void)n_in; (void)out_size;
    const float* x    = (const float*)d_in[0];
    const int*   adj  = (const int*)d_in[1];
    const float* W    = (const float*)d_in[2];
    const float* bias = (const float*)d_in[3];
    float* out = (float*)d_out;

    cudaFuncSetAttribute(edgeconv_fused_kernel,
                         cudaFuncAttributeMaxDynamicSharedMemorySize, SMEM_BYTES);

    edgeconv_xv_kernel<<<(BB * NN) / 64, 256>>>(x);
    edgeconv_prepw_kernel<<<32, 256>>>(W);
    const int tiles = (BB * NN) / TP;   // 1024
    edgeconv_fused_kernel<<<tiles, THREADS, SMEM_BYTES>>>(x, adj, bias, out);
}

// round 13
// speedup vs baseline: 1.1378x; 1.1378x over previous
#include <cuda_runtime.h>
#include <cuda_bf16.h>
#include <cstdint>

// EdgeConv fused, round 13: exact round-10 kernel + smem-staged coalesced
// epilogue (STG wavefronts 2048 -> 768 per block).
// out[p][o] = sum_cc E[p][cc] * Wt[cc][o] + bias[o]
//   E = [gsum | x], Wt[cc<64] = W[o][cc]/20, Wt[cc>=64] = W[o][cc]-W[o][cc-64]

#define BB 4
#define NN 32768
#define KK 20
#define CC 64
#define C2 128
#define OUTD 64
#define TP 128
#define THREADS 256
#define ROWB 256        // A/W image row bytes; swizzle k' = (k&8)|((k^row)&7)

// smem byte offsets (main kernel)
#define OFF_W_HI  0
#define OFF_W_LO  16384
#define OFF_A_HI  32768
#define OFF_A_LO  65536
#define OFF_SCR   98304           // 8 warps x 256 floats (2 bufs x [A:64|B:64])
#define OFF_BIAS  106496
#define SMEM_BYTES (OFF_BIAS + 256)   // 106752 -> 2 CTAs/SM

// epilogue staging reuses [OFF_A_HI, OFF_A_HI+36864) after GEMM
#define STG_STRIDE 72   // floats per staged row

__device__ float g_xv[(size_t)BB * NN * 20];               // variant table 10.5 MB
__device__ __align__(16) unsigned short g_Whi[OUTD * C2];  // swizzled W images
__device__ __align__(16) unsigned short g_Wlo[OUTD * C2];

// ---------------- helpers ----------------
__device__ __forceinline__ unsigned smem_u32(const void* p) {
    unsigned a;
    asm("{ .reg .u64 t; cvta.to.shared.u64 t, %1; cvt.u32.u64 %0, t; }" : "=r"(a) : "l"(p));
    return a;
}
__device__ __forceinline__ void ldsm4(unsigned* r, unsigned addr) {
    asm volatile("ldmatrix.sync.aligned.m8n8.x4.shared.b16 {%0,%1,%2,%3}, [%4];"
                 : "=r"(r[0]), "=r"(r[1]), "=r"(r[2]), "=r"(r[3]) : "r"(addr));
}
__device__ __forceinline__ void mma16816(float* d, const unsigned* a,
                                         unsigned b0, unsigned b1) {
    asm volatile(
        "mma.sync.aligned.m16n8k16.row.col.f32.bf16.bf16.f32 "
        "{%0,%1,%2,%3}, {%4,%5,%6,%7}, {%8,%9}, {%0,%1,%2,%3};"
        : "+f"(d[0]), "+f"(d[1]), "+f"(d[2]), "+f"(d[3])
        : "r"(a[0]), "r"(a[1]), "r"(a[2]), "r"(a[3]), "r"(b0), "r"(b1));
}
__device__ __forceinline__ unsigned pack_hi(float a, float b, float& ra, float& rb) {
    __nv_bfloat16 ha = __float2bfloat16(a), hb = __float2bfloat16(b);
    ra = a - __bfloat162float(ha);
    rb = b - __bfloat162float(hb);
    return ((unsigned)__bfloat16_as_ushort(hb) << 16) | (unsigned)__bfloat16_as_ushort(ha);
}
__device__ __forceinline__ unsigned pack_lo(float ra, float rb) {
    __nv_bfloat16 la = __float2bfloat16(ra);
    __nv_bfloat16 lb = __float2bfloat16(rb);
    return ((unsigned)__bfloat16_as_ushort(lb) << 16) | (unsigned)__bfloat16_as_ushort(la);
}
__device__ __forceinline__ unsigned swz(int r, int k) {
    return (unsigned)(r * ROWB + (((k & 8) | ((k ^ r) & 7)) << 4));
}

// ---------------- prep 1: window-variant table (round-10 version) -----------
__global__ __launch_bounds__(256)
void edgeconv_xv_kernel(const float* __restrict__ x)
{
    __shared__ float s4[64 * 16];
    const int tid = threadIdx.x;
    const int R0  = blockIdx.x * 64;

    const float4* __restrict__ x4 = (const float4*)x + (size_t)R0 * 16;
    #pragma unroll
    for (int i = 0; i < 4; ++i) {
        int idx = tid + 256 * i;
        float4 v = x4[idx];
        s4[idx] = (v.x + v.y) + (v.z + v.w);
    }
    __syncthreads();

    #pragma unroll
    for (int pass = 0; pass < 2; ++pass) {
        int item = tid + pass * 256;
        if (item < 320) {
            int r = item / 5;
            int v = item - 5 * r;
            const float* s = &s4[r * 16];
            const int i1 = 4 - v, i2 = 9 - v, i3 = 14 - v;
            float cum = 0.0f, P1 = 0.0f, P2 = 0.0f, P3 = 0.0f;
            #pragma unroll
            for (int i = 0; i < 16; ++i) {
                cum += s[i];
                if (i == i1) P1 = cum;
                if (i == i2) P2 = cum;
                if (i == i3) P3 = cum;
            }
            float4 o;
            o.x = P1;
            o.y = P2 - P1;
            o.z = P3 - P2;
            o.w = cum - P3;
            *(float4*)&g_xv[(size_t)(R0 + r) * 20 + 4 * v] = o;
        }
    }
}

// ---------------- prep 2: combined weights -> bf16 hi/lo swizzled images ----
__global__ void edgeconv_prepw_kernel(const float* __restrict__ W)
{
    int i = blockIdx.x * blockDim.x + threadIdx.x;
    if (i < OUTD * C2) {
        int o = i >> 7, cc = i & 127;
        float w = W[o * C2 + cc];
        if (cc < CC) w *= (1.0f / (float)KK);
        else         w -= W[o * C2 + (cc - CC)];
        __nv_bfloat16 h = __float2bfloat16(w);
        __nv_bfloat16 l = __float2bfloat16(w - __bfloat162float(h));
        unsigned byteoff = swz(o, cc >> 3) + ((cc & 7) << 1);
        g_Whi[byteoff >> 1] = __bfloat16_as_ushort(h);
        g_Wlo[byteoff >> 1] = __bfloat16_as_ushort(l);
    }
}

// ---------------- main fused kernel ----------------
__global__ __launch_bounds__(THREADS, 2)
void edgeconv_fused_kernel(const float* __restrict__ x,
                           const int* __restrict__ adj,
                           const float* __restrict__ bias,
                           float* __restrict__ out)
{
    extern __shared__ __align__(16) char smem[];
    const unsigned smem_base = smem_u32(smem);

    const int tid = threadIdx.x;
    const int wid = tid >> 5;
    const int lid = tid & 31;
    const int gp0 = blockIdx.x * TP;
    const int b   = gp0 >> 15;
    const int n0  = gp0 & (NN - 1);

    // ---- copy prepped W images + bias; zero scatter planes ----
    {
        const uint4* sh = (const uint4*)g_Whi;
        const uint4* sl = (const uint4*)g_Wlo;
        uint4* dh = (uint4*)(smem + OFF_W_HI);
        uint4* dl = (uint4*)(smem + OFF_W_LO);
        #pragma unroll
        for (int i = tid; i < (OUTD * C2) / 8; i += THREADS) { dh[i] = sh[i]; dl[i] = sl[i]; }
    }
    if (tid < OUTD) ((float*)(smem + OFF_BIAS))[tid] = bias[tid];

    float* __restrict__ sw = (float*)(smem + OFF_SCR) + wid * 256;
    #pragma unroll
    for (int i = lid; i < 256; i += 32) sw[i] = 0.0f;   // plane B stays 0 where unused
    __syncwarp();

    // ---- gather: warp owns points [16*wid, 16*wid+16), processed in pairs ----
    const float4* __restrict__ xv4 = (const float4*)g_xv + (size_t)b * NN * 5;
    const float2* __restrict__ xb2 = (const float2*)(x + (size_t)b * NN * CC);

    const bool act = (lid < KK);
    const int  vS  = act ? (lid % 5) : 0;
    const int  c0  = act ? ((16 * lid - vS) / 5) : 0;     // first window of slot
    const int  a3  = ((vS == 4) ? 0 : 64) + c0 + 3;       // k=3 target (A or B plane)

    int a[16];
    #pragma unroll
    for (int pi = 0; pi < 16; ++pi) {
        int gp = gp0 + 16 * wid + pi;
        a[pi] = act ? adj[(size_t)gp * KK + lid] : 0;
    }

    // prime the pipeline with pair 0
    float4 f0 = make_float4(0.f, 0.f, 0.f, 0.f);
    float4 f1 = make_float4(0.f, 0.f, 0.f, 0.f);
    if (act) {
        f0 = xv4[(size_t)a[0] * 5 + vS];
        f1 = xv4[(size_t)a[1] * 5 + vS];
    }
    float2 xc0 = xb2[(size_t)(n0 + 16 * wid + 0) * 32 + lid];
    float2 xc1 = xb2[(size_t)(n0 + 16 * wid + 1) * 32 + lid];

    #pragma unroll 1
    for (int pi = 0; pi < 16; pi += 2) {
        const int p = 16 * wid + pi;
        float* buf0 = sw;
        float* buf1 = sw + 128;

        if (act) {
            buf0[c0]     = f0.x;
            buf0[c0 + 1] = f0.y;
            buf0[c0 + 2] = f0.z;
            buf0[a3]     = f0.w;
            buf1[c0]     = f1.x;
            buf1[c0 + 1] = f1.y;
            buf1[c0 + 2] = f1.z;
            buf1[a3]     = f1.w;
        }

        // prefetch next pair (full-iteration lead: 4 scattered LDGs in flight)
        float4 fn0 = make_float4(0.f, 0.f, 0.f, 0.f);
        float4 fn1 = make_float4(0.f, 0.f, 0.f, 0.f);
        float2 xn0 = make_float2(0.f, 0.f);
        float2 xn1 = make_float2(0.f, 0.f);
        if (pi < 14) {
            if (act) {
                fn0 = xv4[(size_t)a[pi + 2] * 5 + vS];
                fn1 = xv4[(size_t)a[pi + 3] * 5 + vS];
            }
            xn0 = xb2[(size_t)(n0 + p + 2) * 32 + lid];
            xn1 = xb2[(size_t)(n0 + p + 3) * 32 + lid];
        }

        __syncwarp();

        // read both points' windows
        float2 ga0 = *(const float2*)&buf0[2 * lid];
        float2 gb0 = *(const float2*)&buf0[64 + 2 * lid];
        float2 ga1 = *(const float2*)&buf1[2 * lid];
        float2 gb1 = *(const float2*)&buf1[64 + 2 * lid];
        float wA0 = ga0.x + gb0.x, wB0 = ga0.y + gb0.y;
        float wA1 = ga1.x + gb1.x, wB1 = ga1.y + gb1.y;

        // pack + store A images for point p
        {
            float rg0, rg1, rx0, rx1;
            unsigned hp_g = pack_hi(wA0, wB0, rg0, rg1);
            unsigned hp_x = pack_hi(xc0.x, xc0.y, rx0, rx1);
            unsigned lp_g = pack_lo(rg0, rg1);
            unsigned lp_x = pack_lo(rx0, rx1);
            const int w4 = (lid & 3) << 2;
            unsigned offg = swz(p, lid >> 2)       + w4;
            unsigned offx = swz(p, 8 + (lid >> 2)) + w4;
            *(unsigned*)(smem + OFF_A_HI + offg) = hp_g;
            *(unsigned*)(smem + OFF_A_LO + offg) = lp_g;
            *(unsigned*)(smem + OFF_A_HI + offx) = hp_x;
            *(unsigned*)(smem + OFF_A_LO + offx) = lp_x;
        }
        // point p+1
        {
            float rg0, rg1, rx0, rx1;
            unsigned hp_g = pack_hi(wA1, wB1, rg0, rg1);
            unsigned hp_x = pack_hi(xc1.x, xc1.y, rx0, rx1);
            unsigned lp_g = pack_lo(rg0, rg1);
            unsigned lp_x = pack_lo(rx0, rx1);
            const int w4 = (lid & 3) << 2;
            unsigned offg = swz(p + 1, lid >> 2)       + w4;
            unsigned offx = swz(p + 1, 8 + (lid >> 2)) + w4;
            *(unsigned*)(smem + OFF_A_HI + offg) = hp_g;
            *(unsigned*)(smem + OFF_A_LO + offg) = lp_g;
            *(unsigned*)(smem + OFF_A_HI + offx) = hp_x;
            *(unsigned*)(smem + OFF_A_LO + offx) = lp_x;
        }

        __syncwarp();   // WAR: planes reused next iteration

        f0 = fn0; f1 = fn1; xc0 = xn0; xc1 = xn1;
    }

    __syncthreads();

    // ---- GEMM: warps 4M x 2N, warp tile 32x32, K=128, bf16 3-product split ----
    const int mg = wid & 3;
    const int ng = wid >> 2;
    const int lrow  = (lid & 7) + 8 * ((lid >> 3) & 1);
    const int khalf = lid >> 4;

    const int rA0 = 32 * mg + lrow;
    const int rB0 = 32 * ng + (lid & 15);

    float d[2][4][4];
    #pragma unroll
    for (int mt = 0; mt < 2; ++mt)
        #pragma unroll
        for (int nt = 0; nt < 4; ++nt)
            #pragma unroll
            for (int e = 0; e < 4; ++e) d[mt][nt][e] = 0.0f;

    #pragma unroll 2
    for (int ks = 0; ks < 8; ++ks) {
        const int k = 2 * ks + khalf;
        const unsigned a0 = smem_base + OFF_A_HI + swz(rA0, k);
        const unsigned a1 = smem_base + OFF_A_HI + swz(rA0 + 16, k);
        const unsigned b0 = smem_base + OFF_W_HI + swz(rB0, k);
        const unsigned b1 = smem_base + OFF_W_HI + swz(rB0 + 16, k);

        unsigned ah[2][4], al[2][4];
        ldsm4(ah[0], a0);
        ldsm4(ah[1], a1);
        ldsm4(al[0], a0 + (OFF_A_LO - OFF_A_HI));
        ldsm4(al[1], a1 + (OFF_A_LO - OFF_A_HI));

        unsigned bh01[4], bh23[4], bl01[4], bl23[4];
        ldsm4(bh01, b0);
        ldsm4(bh23, b1);
        ldsm4(bl01, b0 + (OFF_W_LO - OFF_W_HI));
        ldsm4(bl23, b1 + (OFF_W_LO - OFF_W_HI));

        unsigned bhf[4][2] = {{bh01[0], bh01[2]}, {bh01[1], bh01[3]},
                              {bh23[0], bh23[2]}, {bh23[1], bh23[3]}};
        unsigned blf[4][2] = {{bl01[0], bl01[2]}, {bl01[1], bl01[3]},
                              {bl23[0], bl23[2]}, {bl23[1], bl23[3]}};

        #pragma unroll
        for (int mt = 0; mt < 2; ++mt) {
            #pragma unroll
            for (int nt = 0; nt < 4; ++nt) {
                mma16816(d[mt][nt], ah[mt], bhf[nt][0], bhf[nt][1]);
                mma16816(d[mt][nt], al[mt], bhf[nt][0], bhf[nt][1]);
                mma16816(d[mt][nt], ah[mt], blf[nt][0], blf[nt][1]);
            }
        }
    }

    // ---- epilogue: stage (bias added) into smem, then coalesced STG.128 ----
    __syncthreads();   // A images dead; reuse region for staging
    float* __restrict__ stage = (float*)(smem + OFF_A_HI);   // 128 x 72 floats
    const float* sBias = (const float*)(smem + OFF_BIAS);
    const int g  = lid >> 2;
    const int oc = 2 * (lid & 3);
    #pragma unroll
    for (int mt = 0; mt < 2; ++mt) {
        const int row = 32 * mg + 16 * mt + g;
        #pragma unroll
        for (int nt = 0; nt < 4; ++nt) {
            const int o = 32 * ng + 8 * nt + oc;
            float2 bb = *(const float2*)&sBias[o];
            float2 r0, r1;
            r0.x = d[mt][nt][0] + bb.x;  r0.y = d[mt][nt][1] + bb.y;
            r1.x = d[mt][nt][2] + bb.x;  r1.y = d[mt][nt][3] + bb.y;
            *(float2*)&stage[row * STG_STRIDE + o]       = r0;
            *(float2*)&stage[(row + 8) * STG_STRIDE + o] = r1;
        }
    }
    __syncthreads();

    // coalesced: thread t, iter j -> float4 index q = t + 256j  (128 rows x 16)
    float4* __restrict__ out4 = (float4*)(out + (size_t)gp0 * OUTD);
    #pragma unroll
    for (int j = 0; j < 8; ++j) {
        int q   = tid + 256 * j;
        int row = q >> 4;
        int c4  = q & 15;
        out4[q] = *(const float4*)&stage[row * STG_STRIDE + 4 * c4];
    }
}

extern "C" void kernel_launch(void* const* d_in, const int* in_sizes, int n_in,
                              void* d_out, int out_size)
{
    (void)in_sizes; (void)n_in; (void)out_size;
    const float* x    = (const float*)d_in[0];
    const int*   adj  = (const int*)d_in[1];
    const float* W    = (const float*)d_in[2];
    const float* bias = (const float*)d_in[3];
    float* out = (float*)d_out;

    cudaFuncSetAttribute(edgeconv_fused_kernel,
                         cudaFuncAttributeMaxDynamicSharedMemorySize, SMEM_BYTES);

    edgeconv_xv_kernel<<<(BB * NN) / 64, 256>>>(x);
    edgeconv_prepw_kernel<<<32, 256>>>(W);
    const int tiles = (BB * NN) / TP;   // 1024
    edgeconv_fused_kernel<<<tiles, THREADS, SMEM_BYTES>>>(x, adj, bias, out);
}

// round 14
// speedup vs baseline: 1.1416x; 1.0033x over previous
#include <cuda_runtime.h>
#include <cuda_bf16.h>
#include <cstdint>

// EdgeConv fused, round 14: round-10 main kernel (best known) + merged prep
// with parallel segment-sum window computation (breaks serial prefix chain).
// out[p][o] = sum_cc E[p][cc] * Wt[cc][o] + bias[o]
//   E = [gsum | x], Wt[cc<64] = W[o][cc]/20, Wt[cc>=64] = W[o][cc]-W[o][cc-64]

#define BB 4
#define NN 32768
#define KK 20
#define CC 64
#define C2 128
#define OUTD 64
#define TP 128
#define THREADS 256
#define ROWB 256        // A/W image row bytes; swizzle k' = (k&8)|((k^row)&7)

// smem byte offsets (main kernel)
#define OFF_W_HI  0
#define OFF_W_LO  16384
#define OFF_A_HI  32768
#define OFF_A_LO  65536
#define OFF_SCR   98304           // 8 warps x 256 floats (2 bufs x [A:64|B:64])
#define OFF_BIAS  106496
#define SMEM_BYTES (OFF_BIAS + 256)   // 106752 -> 2 CTAs/SM

#define XV_BLOCKS ((BB * NN) / 64)    // 2048

__device__ float g_xv[(size_t)BB * NN * 20];               // variant table 10.5 MB
__device__ __align__(16) unsigned short g_Whi[OUTD * C2];  // swizzled W images
__device__ __align__(16) unsigned short g_Wlo[OUTD * C2];

// ---------------- helpers ----------------
__device__ __forceinline__ unsigned smem_u32(const void* p) {
    unsigned a;
    asm("{ .reg .u64 t; cvta.to.shared.u64 t, %1; cvt.u32.u64 %0, t; }" : "=r"(a) : "l"(p));
    return a;
}
__device__ __forceinline__ void ldsm4(unsigned* r, unsigned addr) {
    asm volatile("ldmatrix.sync.aligned.m8n8.x4.shared.b16 {%0,%1,%2,%3}, [%4];"
                 : "=r"(r[0]), "=r"(r[1]), "=r"(r[2]), "=r"(r[3]) : "r"(addr));
}
__device__ __forceinline__ void mma16816(float* d, const unsigned* a,
                                         unsigned b0, unsigned b1) {
    asm volatile(
        "mma.sync.aligned.m16n8k16.row.col.f32.bf16.bf16.f32 "
        "{%0,%1,%2,%3}, {%4,%5,%6,%7}, {%8,%9}, {%0,%1,%2,%3};"
        : "+f"(d[0]), "+f"(d[1]), "+f"(d[2]), "+f"(d[3])
        : "r"(a[0]), "r"(a[1]), "r"(a[2]), "r"(a[3]), "r"(b0), "r"(b1));
}
__device__ __forceinline__ unsigned pack_hi(float a, float b, float& ra, float& rb) {
    __nv_bfloat16 ha = __float2bfloat16(a), hb = __float2bfloat16(b);
    ra = a - __bfloat162float(ha);
    rb = b - __bfloat162float(hb);
    return ((unsigned)__bfloat16_as_ushort(hb) << 16) | (unsigned)__bfloat16_as_ushort(ha);
}
__device__ __forceinline__ unsigned pack_lo(float ra, float rb) {
    __nv_bfloat16 la = __float2bfloat16(ra);
    __nv_bfloat16 lb = __float2bfloat16(rb);
    return ((unsigned)__bfloat16_as_ushort(lb) << 16) | (unsigned)__bfloat16_as_ushort(la);
}
__device__ __forceinline__ unsigned swz(int r, int k) {
    return (unsigned)(r * ROWB + (((k & 8) | ((k ^ r) & 7)) << 4));
}

// ---------------- merged prep: xv table (blocks < XV_BLOCKS) + W images ------
// xv[row][v] = 4 independent segment sums of the row's 16 4-chunk sums:
//   o.x = sum s[0 .. 4-v]       (predicated 5-term)
//   o.y = sum s[5-v .. 9-v]     (fixed 5-term tree)
//   o.z = sum s[10-v .. 14-v]   (fixed 5-term tree)
//   o.w = sum s[15-v .. 15]     (predicated 5-term)
__global__ __launch_bounds__(256)
void edgeconv_prep_kernel(const float* __restrict__ x, const float* __restrict__ W)
{
    const int tid = threadIdx.x;

    if (blockIdx.x >= XV_BLOCKS) {
        // ---- W branch: combined weights -> bf16 hi/lo swizzled images ----
        int i = (blockIdx.x - XV_BLOCKS) * 256 + tid;
        if (i < OUTD * C2) {
            int o = i >> 7, cc = i & 127;
            float w = W[o * C2 + cc];
            if (cc < CC) w *= (1.0f / (float)KK);
            else         w -= W[o * C2 + (cc - CC)];
            __nv_bfloat16 h = __float2bfloat16(w);
            __nv_bfloat16 l = __float2bfloat16(w - __bfloat162float(h));
            unsigned byteoff = swz(o, cc >> 3) + ((cc & 7) << 1);
            g_Whi[byteoff >> 1] = __bfloat16_as_ushort(h);
            g_Wlo[byteoff >> 1] = __bfloat16_as_ushort(l);
        }
        return;
    }

    __shared__ float s4[64 * 16];
    const int R0 = blockIdx.x * 64;

    // phase 1: coalesced loads, 4-chunk sums
    const float4* __restrict__ x4 = (const float4*)x + (size_t)R0 * 16;
    #pragma unroll
    for (int i = 0; i < 4; ++i) {
        int idx = tid + 256 * i;
        float4 v = x4[idx];
        s4[idx] = (v.x + v.y) + (v.z + v.w);
    }
    __syncthreads();

    // phase 2: 320 (row, variant) items; independent short-chain segment sums
    #pragma unroll
    for (int pass = 0; pass < 2; ++pass) {
        int item = tid + pass * 256;
        if (item < 320) {
            int r = item / 5;
            int v = item - 5 * r;
            const float* s = &s4[r * 16];

            // o.x = s[0..4-v] : predicated descending
            float ox = s[0];
            if (v < 4) ox += s[1];
            if (v < 3) ox += s[2];
            if (v < 2) ox += s[3];
            if (v < 1) ox += s[4];

            // o.w = s[15-v..15] : predicated ascending
            float ow = s[15];
            if (v > 0) ow += s[14];
            if (v > 1) ow += s[13];
            if (v > 2) ow += s[12];
            if (v > 3) ow += s[11];

            // o.y, o.z : fixed 5-term tree sums at runtime offset
            const float* sy = s + (5 - v);
            float oy = ((sy[0] + sy[1]) + (sy[2] + sy[3])) + sy[4];
            const float* sz = s + (10 - v);
            float oz = ((sz[0] + sz[1]) + (sz[2] + sz[3])) + sz[4];

            float4 o;
            o.x = ox; o.y = oy; o.z = oz; o.w = ow;
            *(float4*)&g_xv[(size_t)(R0 + r) * 20 + 4 * v] = o;
        }
    }
}

// ---------------- main fused kernel (round-10, best known) ----------------
__global__ __launch_bounds__(THREADS, 2)
void edgeconv_fused_kernel(const float* __restrict__ x,
                           const int* __restrict__ adj,
                           const float* __restrict__ bias,
                           float* __restrict__ out)
{
    extern __shared__ __align__(16) char smem[];
    const unsigned smem_base = smem_u32(smem);

    const int tid = threadIdx.x;
    const int wid = tid >> 5;
    const int lid = tid & 31;
    const int gp0 = blockIdx.x * TP;
    const int b   = gp0 >> 15;
    const int n0  = gp0 & (NN - 1);

    // ---- copy prepped W images + bias; zero scatter planes ----
    {
        const uint4* sh = (const uint4*)g_Whi;
        const uint4* sl = (const uint4*)g_Wlo;
        uint4* dh = (uint4*)(smem + OFF_W_HI);
        uint4* dl = (uint4*)(smem + OFF_W_LO);
        #pragma unroll
        for (int i = tid; i < (OUTD * C2) / 8; i += THREADS) { dh[i] = sh[i]; dl[i] = sl[i]; }
    }
    if (tid < OUTD) ((float*)(smem + OFF_BIAS))[tid] = bias[tid];

    float* __restrict__ sw = (float*)(smem + OFF_SCR) + wid * 256;
    #pragma unroll
    for (int i = lid; i < 256; i += 32) sw[i] = 0.0f;   // plane B stays 0 where unused
    __syncwarp();

    // ---- gather: warp owns points [16*wid, 16*wid+16), processed in pairs ----
    const float4* __restrict__ xv4 = (const float4*)g_xv + (size_t)b * NN * 5;
    const float2* __restrict__ xb2 = (const float2*)(x + (size_t)b * NN * CC);

    const bool act = (lid < KK);
    const int  vS  = act ? (lid % 5) : 0;
    const int  c0  = act ? ((16 * lid - vS) / 5) : 0;     // first window of slot
    const int  a3  = ((vS == 4) ? 0 : 64) + c0 + 3;       // k=3 target (A or B plane)

    int a[16];
    #pragma unroll
    for (int pi = 0; pi < 16; ++pi) {
        int gp = gp0 + 16 * wid + pi;
        a[pi] = act ? adj[(size_t)gp * KK + lid] : 0;
    }

    // prime the pipeline with pair 0
    float4 f0 = make_float4(0.f, 0.f, 0.f, 0.f);
    float4 f1 = make_float4(0.f, 0.f, 0.f, 0.f);
    if (act) {
        f0 = xv4[(size_t)a[0] * 5 + vS];
        f1 = xv4[(size_t)a[1] * 5 + vS];
    }
    float2 xc0 = xb2[(size_t)(n0 + 16 * wid + 0) * 32 + lid];
    float2 xc1 = xb2[(size_t)(n0 + 16 * wid + 1) * 32 + lid];

    #pragma unroll 1
    for (int pi = 0; pi < 16; pi += 2) {
        const int p = 16 * wid + pi;
        float* buf0 = sw;
        float* buf1 = sw + 128;

        if (act) {
            buf0[c0]     = f0.x;
            buf0[c0 + 1] = f0.y;
            buf0[c0 + 2] = f0.z;
            buf0[a3]     = f0.w;
            buf1[c0]     = f1.x;
            buf1[c0 + 1] = f1.y;
            buf1[c0 + 2] = f1.z;
            buf1[a3]     = f1.w;
        }

        // prefetch next pair (4 scattered LDGs in flight)
        float4 fn0 = make_float4(0.f, 0.f, 0.f, 0.f);
        float4 fn1 = make_float4(0.f, 0.f, 0.f, 0.f);
        float2 xn0 = make_float2(0.f, 0.f);
        float2 xn1 = make_float2(0.f, 0.f);
        if (pi < 14) {
            if (act) {
                fn0 = xv4[(size_t)a[pi + 2] * 5 + vS];
                fn1 = xv4[(size_t)a[pi + 3] * 5 + vS];
            }
            xn0 = xb2[(size_t)(n0 + p + 2) * 32 + lid];
            xn1 = xb2[(size_t)(n0 + p + 3) * 32 + lid];
        }

        __syncwarp();

        float2 ga0 = *(const float2*)&buf0[2 * lid];
        float2 gb0 = *(const float2*)&buf0[64 + 2 * lid];
        float2 ga1 = *(const float2*)&buf1[2 * lid];
        float2 gb1 = *(const float2*)&buf1[64 + 2 * lid];
        float wA0 = ga0.x + gb0.x, wB0 = ga0.y + gb0.y;
        float wA1 = ga1.x + gb1.x, wB1 = ga1.y + gb1.y;

        {
            float rg0, rg1, rx0, rx1;
            unsigned hp_g = pack_hi(wA0, wB0, rg0, rg1);
            unsigned hp_x = pack_hi(xc0.x, xc0.y, rx0, rx1);
            unsigned lp_g = pack_lo(rg0, rg1);
            unsigned lp_x = pack_lo(rx0, rx1);
            const int w4 = (lid & 3) << 2;
            unsigned offg = swz(p, lid >> 2)       + w4;
            unsigned offx = swz(p, 8 + (lid >> 2)) + w4;
            *(unsigned*)(smem + OFF_A_HI + offg) = hp_g;
            *(unsigned*)(smem + OFF_A_LO + offg) = lp_g;
            *(unsigned*)(smem + OFF_A_HI + offx) = hp_x;
            *(unsigned*)(smem + OFF_A_LO + offx) = lp_x;
        }
        {
            float rg0, rg1, rx0, rx1;
            unsigned hp_g = pack_hi(wA1, wB1, rg0, rg1);
            unsigned hp_x = pack_hi(xc1.x, xc1.y, rx0, rx1);
            unsigned lp_g = pack_lo(rg0, rg1);
            unsigned lp_x = pack_lo(rx0, rx1);
            const int w4 = (lid & 3) << 2;
            unsigned offg = swz(p + 1, lid >> 2)       + w4;
            unsigned offx = swz(p + 1, 8 + (lid >> 2)) + w4;
            *(unsigned*)(smem + OFF_A_HI + offg) = hp_g;
            *(unsigned*)(smem + OFF_A_LO + offg) = lp_g;
            *(unsigned*)(smem + OFF_A_HI + offx) = hp_x;
            *(unsigned*)(smem + OFF_A_LO + offx) = lp_x;
        }

        __syncwarp();   // WAR: planes reused next iteration

        f0 = fn0; f1 = fn1; xc0 = xn0; xc1 = xn1;
    }

    __syncthreads();

    // ---- GEMM: warps 4M x 2N, warp tile 32x32, K=128, bf16 3-product split ----
    const int mg = wid & 3;
    const int ng = wid >> 2;
    const int lrow  = (lid & 7) + 8 * ((lid >> 3) & 1);
    const int khalf = lid >> 4;

    const int rA0 = 32 * mg + lrow;
    const int rB0 = 32 * ng + (lid & 15);

    float d[2][4][4];
    #pragma unroll
    for (int mt = 0; mt < 2; ++mt)
        #pragma unroll
        for (int nt = 0; nt < 4; ++nt)
            #pragma unroll
            for (int e = 0; e < 4; ++e) d[mt][nt][e] = 0.0f;

    #pragma unroll 2
    for (int ks = 0; ks < 8; ++ks) {
        const int k = 2 * ks + khalf;
        const unsigned a0 = smem_base + OFF_A_HI + swz(rA0, k);
        const unsigned a1 = smem_base + OFF_A_HI + swz(rA0 + 16, k);
        const unsigned b0 = smem_base + OFF_W_HI + swz(rB0, k);
        const unsigned b1 = smem_base + OFF_W_HI + swz(rB0 + 16, k);

        unsigned ah[2][4], al[2][4];
        ldsm4(ah[0], a0);
        ldsm4(ah[1], a1);
        ldsm4(al[0], a0 + (OFF_A_LO - OFF_A_HI));
        ldsm4(al[1], a1 + (OFF_A_LO - OFF_A_HI));

        unsigned bh01[4], bh23[4], bl01[4], bl23[4];
        ldsm4(bh01, b0);
        ldsm4(bh23, b1);
        ldsm4(bl01, b0 + (OFF_W_LO - OFF_W_HI));
        ldsm4(bl23, b1 + (OFF_W_LO - OFF_W_HI));

        unsigned bhf[4][2] = {{bh01[0], bh01[2]}, {bh01[1], bh01[3]},
                              {bh23[0], bh23[2]}, {bh23[1], bh23[3]}};
        unsigned blf[4][2] = {{bl01[0], bl01[2]}, {bl01[1], bl01[3]},
                              {bl23[0], bl23[2]}, {bl23[1], bl23[3]}};

        #pragma unroll
        for (int mt = 0; mt < 2; ++mt) {
            #pragma unroll
            for (int nt = 0; nt < 4; ++nt) {
                mma16816(d[mt][nt], ah[mt], bhf[nt][0], bhf[nt][1]);
                mma16816(d[mt][nt], al[mt], bhf[nt][0], bhf[nt][1]);
                mma16816(d[mt][nt], ah[mt], blf[nt][0], blf[nt][1]);
            }
        }
    }

    // ---- epilogue: bias + direct store (round-10) ----
    const float* sBias = (const float*)(smem + OFF_BIAS);
    const int g  = lid >> 2;
    const int oc = 2 * (lid & 3);
    #pragma unroll
    for (int mt = 0; mt < 2; ++mt) {
        const int prow = gp0 + 32 * mg + 16 * mt + g;
        #pragma unroll
        for (int nt = 0; nt < 4; ++nt) {
            const int o = 32 * ng + 8 * nt + oc;
            float2 bb = *(const float2*)&sBias[o];
            float2 r0, r1;
            r0.x = d[mt][nt][0] + bb.x;  r0.y = d[mt][nt][1] + bb.y;
            r1.x = d[mt][nt][2] + bb.x;  r1.y = d[mt][nt][3] + bb.y;
            *(float2*)&out[(size_t)prow * OUTD + o]       = r0;
            *(float2*)&out[(size_t)(prow + 8) * OUTD + o] = r1;
        }
    }
}

extern "C" void kernel_launch(void* const* d_in, const int* in_sizes, int n_in,
                              void* d_out, int out_size)
{
    (void)in_sizes; (void)n_in; (void)out_size;
    const float* x    = (const float*)d_in[0];
    const int*   adj  = (const int*)d_in[1];
    const float* W    = (const float*)d_in[2];
    const float* bias = (const float*)d_in[3];
    float* out = (float*)d_out;

    cudaFuncSetAttribute(edgeconv_fused_kernel,
                         cudaFuncAttributeMaxDynamicSharedMemorySize, SMEM_BYTES);

    edgeconv_prep_kernel<<<XV_BLOCKS + 32, 256>>>(x, W);
    const int tiles = (BB * NN) / TP;   // 1024
    edgeconv_fused_kernel<<<tiles, THREADS, SMEM_BYTES>>>(x, adj, bias, out);
}